// round 9
// baseline (speedup 1.0000x reference)
#include <cuda_runtime.h>
#include <math.h>
#include <stdint.h>

// Problem constants
#define BB 128      // batch
#define TT 128      // time steps
#define FF 128      // features
#define DD 512      // hidden
#define NG 2048     // 4*D
#define KC 32       // K-chunk (elements)
#define NSTAGE 4
#define NBLOCKS 128

// block tile: M=64 (2 M-halves), N=32 (64 N-groups) -> grid 128
#define BM 64
#define BN 32

// padded strides (floats)
#define ALD 36
#define BLD 36
#define A_ST (BM*ALD)                           // 2304 floats
#define B_ST (BN*BLD)                           // 1152 floats
#define STAGE_FLOATS (A_ST + B_ST)              // 3456
#define SMEM_BYTES (NSTAGE*STAGE_FLOATS*4)      // 55296
#define ZLD 34

// ---- scratch (device globals; no allocation allowed) ----
__device__ float g_h [BB*DD];
__device__ float g_c [BB*DD];
__device__ float g_h0[BB*DD];
__device__ float g_c0[BB*DD];
__device__ float g_hA[BB*DD];
__device__ float g_cA[BB*DD];
__device__ float g_hB[BB*DD];
__device__ float g_cB[BB*DD];
__device__ float g_Wsum[DD*NG];
// permuted+tf32-rounded weights: [n][k], n = d*4+gate
__device__ float g_pEW0[NG*FF];
__device__ float g_pEU0[NG*DD];
__device__ float g_pW1s[NG*DD];
__device__ float g_pDW0[NG*FF];
__device__ float g_pDU0[NG*DD];
__device__ float g_pDW1[NG*DD];
__device__ float g_pDU1[NG*DD];
// permuted biases
__device__ float g_pbE0[NG];
__device__ float g_pbE1[NG];
__device__ float g_pbD0[NG];
__device__ float g_pbD1[NG];
// tf32-rounded inputs / feedback
__device__ float g_encR[BB*TT*FF];
__device__ float g_x0R [BB*FF];
__device__ float g_xfb [BB*FF];
// grid barrier state
__device__ unsigned g_bar[2];   // [0]=count, [1]=sense

// ---- helpers ----
__device__ __forceinline__ float sigmoidf_(float x) { return 1.0f / (1.0f + expf(-x)); }

__device__ __forceinline__ float rna_tf32(float x) {
    unsigned u;
    asm("cvt.rna.tf32.f32 %0, %1;" : "=r"(u) : "f"(x));
    return __uint_as_float(u);
}

__device__ __forceinline__ unsigned smem_u32(const void* p) {
    return (unsigned)__cvta_generic_to_shared(p);
}

#define CP_ASYNC16(dst_u32, src_ptr) \
    asm volatile("cp.async.cg.shared.global [%0], [%1], 16;\n" :: "r"(dst_u32), "l"(src_ptr))
#define CP_COMMIT() asm volatile("cp.async.commit_group;\n" ::: "memory")
#define CP_WAIT2()  asm volatile("cp.async.wait_group 2;\n" ::: "memory")

__device__ __forceinline__ void mma_tf32(float* d,
    unsigned a0, unsigned a1, unsigned a2, unsigned a3, unsigned b0, unsigned b1)
{
    asm volatile(
        "mma.sync.aligned.m16n8k8.row.col.f32.tf32.tf32.f32 "
        "{%0,%1,%2,%3}, {%4,%5,%6,%7}, {%8,%9}, {%0,%1,%2,%3};"
        : "+f"(d[0]), "+f"(d[1]), "+f"(d[2]), "+f"(d[3])
        : "r"(a0), "r"(a1), "r"(a2), "r"(a3), "r"(b0), "r"(b1));
}

// sense-reversal grid barrier (all NBLOCKS blocks resident; wave-1 placement)
__device__ __forceinline__ void grid_bar(unsigned& sense)
{
    __syncthreads();
    sense ^= 1u;
    if (threadIdx.x == 0) {
        __threadfence();
        unsigned old = atomicAdd(&g_bar[0], 1u);
        if (old == NBLOCKS - 1) {
            g_bar[0] = 0;
            __threadfence();
            *(volatile unsigned*)&g_bar[1] = sense;
        } else {
            while (*(volatile unsigned*)&g_bar[1] != sense) {}
        }
    }
    __syncthreads();
}

// ================= preprocessing kernels =================
__global__ void add_mats_kernel(const float* __restrict__ a, const float* __restrict__ b,
                                float* __restrict__ o, int n) {
    int i = blockIdx.x * blockDim.x + threadIdx.x;
    if (i < n) o[i] = a[i] + b[i];
}

__global__ void round_copy_kernel(const float* __restrict__ s, float* __restrict__ d, int n) {
    int i = blockIdx.x * blockDim.x + threadIdx.x;
    if (i < n) d[i] = rna_tf32(s[i]);
}

// dst[n*K + k] = rna(src[k*2048 + (n&3)*512 + (n>>2)])  (K = 1<<kshift)
__global__ void permute_mat_kernel(const float* __restrict__ src, float* __restrict__ dst,
                                   int K, int kshift) {
    int i = blockIdx.x * blockDim.x + threadIdx.x;
    if (i >= NG * K) return;
    int k = i & (K - 1);
    int n = i >> kshift;
    int g = n & 3, d = n >> 2;
    dst[i] = rna_tf32(src[(size_t)k * NG + g * DD + d]);
}

__global__ void permute_bias_kernel(const float* __restrict__ b, float* __restrict__ pb) {
    int n = blockIdx.x * blockDim.x + threadIdx.x;
    if (n < NG) pb[n] = b[(n & 3) * DD + (n >> 2)];
}

__global__ void round_slice0_kernel(const float* __restrict__ dec_in, float* __restrict__ d) {
    int i = blockIdx.x * blockDim.x + threadIdx.x;
    if (i < BB * FF) {
        int b = i >> 7, f = i & 127;
        d[i] = rna_tf32(dec_in[(size_t)b * TT * FF + f]);
    }
}

// ================= in-kernel LSTM cell (identical math to R8) =================
__device__ __forceinline__ void run_cell(
    float* sm,
    const float* __restrict__ X, int ldx, int K1, const float* __restrict__ BW,
    const float* __restrict__ H, const float* __restrict__ BU, int K2,
    const float* __restrict__ pbias, const float* __restrict__ cin,
    float* __restrict__ hout, float* __restrict__ cout)
{
    const int tid   = threadIdx.x;
    const int lane  = tid & 31;
    const int wid   = tid >> 5;
    const int gid   = lane >> 2;
    const int tidg  = lane & 3;
    const int warpM = wid & 3;
    const int warpN = wid >> 2;
    const int mb    = blockIdx.x & 1;
    const int nb    = blockIdx.x >> 1;
    const int mbase = mb * BM;
    const int nb32  = nb * BN;

    const int nck = (K1 + K2) / KC;

    auto stage = [&](int ck, int s) {
        const int k0 = ck * KC;
        const float* Ap; int lda_, kA; const float* Bp; int kB, ldb;
        if (k0 < K1) { Ap = X; lda_ = ldx; kA = k0;      Bp = BW; kB = k0;      ldb = K1; }
        else         { Ap = H; lda_ = DD;  kA = k0 - K1; Bp = BU; kB = k0 - K1; ldb = K2; }
        float* As = sm + s * STAGE_FLOATS;
        float* Bs = As + A_ST;
        {
            const int row = tid >> 2, q0 = (tid & 3) * 2;
            const float* src = Ap + (size_t)(mbase + row) * lda_ + kA + q0 * 4;
            const unsigned dst = smem_u32(As + row * ALD + q0 * 4);
            CP_ASYNC16(dst,      src);
            CP_ASYNC16(dst + 16, src + 4);
        }
        {
            const int row = tid >> 3, q = tid & 7;
            const float* src = Bp + (size_t)(nb32 + row) * ldb + kB + q * 4;
            const unsigned dst = smem_u32(Bs + row * BLD + q * 4);
            CP_ASYNC16(dst, src);
        }
    };

    float acc[2][4];
    #pragma unroll
    for (int nt = 0; nt < 2; ++nt)
        #pragma unroll
        for (int e = 0; e < 4; ++e) acc[nt][e] = 0.f;

    stage(0, 0); CP_COMMIT();
    stage(1, 1); CP_COMMIT();
    stage(2, 2); CP_COMMIT();

    for (int ck = 0; ck < nck; ++ck) {
        CP_WAIT2();
        __syncthreads();

        const float* As = sm + (ck & 3) * STAGE_FLOATS;
        const float* Bs = As + A_ST;

        #pragma unroll
        for (int ks = 0; ks < 4; ++ks) {
            const int kb = ks * 8;
            const int rb = warpM * 16;
            unsigned a0 = __float_as_uint(As[(rb + gid    ) * ALD + kb + tidg    ]);
            unsigned a1 = __float_as_uint(As[(rb + gid + 8) * ALD + kb + tidg    ]);
            unsigned a2 = __float_as_uint(As[(rb + gid    ) * ALD + kb + tidg + 4]);
            unsigned a3 = __float_as_uint(As[(rb + gid + 8) * ALD + kb + tidg + 4]);
            #pragma unroll
            for (int nt = 0; nt < 2; ++nt) {
                const int nbase = warpN * 16 + nt * 8;
                unsigned b0 = __float_as_uint(Bs[(nbase + gid) * BLD + kb + tidg    ]);
                unsigned b1 = __float_as_uint(Bs[(nbase + gid) * BLD + kb + tidg + 4]);
                mma_tf32(acc[nt], a0, a1, a2, a3, b0, b1);
            }
        }
        __syncthreads();

        if (ck + 3 < nck) stage(ck + 3, (ck + 3) & 3);
        CP_COMMIT();
    }

    // epilogue: fragments -> smem z-tile -> gates
    float* zs = sm;
    #pragma unroll
    for (int nt = 0; nt < 2; ++nt) {
        const int row0 = warpM * 16 + gid;
        const int col0 = warpN * 16 + nt * 8 + 2 * tidg;
        zs[(row0    ) * ZLD + col0    ] = acc[nt][0];
        zs[(row0    ) * ZLD + col0 + 1] = acc[nt][1];
        zs[(row0 + 8) * ZLD + col0    ] = acc[nt][2];
        zs[(row0 + 8) * ZLD + col0 + 1] = acc[nt][3];
    }
    __syncthreads();

    {
        const int rl = tid >> 2;
        const int r  = mbase + rl;
        const int db = (tid & 3) * 2;
        #pragma unroll
        for (int d = 0; d < 2; ++d) {
            const int nl  = (db + d) * 4;
            const int col = nb * 8 + db + d;
            float zi = zs[rl * ZLD + nl + 0] + pbias[nb32 + nl + 0];
            float zf = zs[rl * ZLD + nl + 1] + pbias[nb32 + nl + 1];
            float zg = zs[rl * ZLD + nl + 2] + pbias[nb32 + nl + 2];
            float zo = zs[rl * ZLD + nl + 3] + pbias[nb32 + nl + 3];
            float i  = sigmoidf_(zi);
            float f  = sigmoidf_(zf);
            float g  = fmaxf(zg, 0.f);
            float o  = sigmoidf_(zo);
            float c2 = f * cin[r * DD + col] + i * g;
            cout[r * DD + col] = c2;
            hout[r * DD + col] = rna_tf32(o * fmaxf(c2, 0.f));
        }
    }
    // caller issues grid_bar (which includes __syncthreads) before smem reuse
}

// ================= persistent megakernel =================
__global__ __launch_bounds__(256, 1)
void persist_kernel(const float* __restrict__ dW, const float* __restrict__ db,
                    float* __restrict__ out)
{
    extern __shared__ __align__(16) float sm[];
    const int tid = threadIdx.x;
    unsigned sense = 0;

    // ---------------- Encoder: 128 steps, 2 layers ----------------
    for (int t = 0; t < TT; ++t) {
        run_cell(sm, g_encR + (size_t)t * FF, TT * FF, FF, g_pEW0,
                 g_h, g_pEU0, DD, g_pbE0, g_c, g_h0, g_c0);
        grid_bar(sense);
        // layer 1: x == h == h0 => z = h0@(W1+U1)
        run_cell(sm, g_h0, DD, DD, g_pW1s,
                 (const float*)nullptr, (const float*)nullptr, 0,
                 g_pbE1, g_c0, g_h, g_c);
        grid_bar(sense);
    }

    // ---------------- Decoder: 128 steps, 2 layers + dense ----------------
    for (int t = 0; t < TT; ++t) {
        const float* hcur = (t == 0) ? g_h : ((t & 1) ? g_hA : g_hB);
        const float* ccur = (t == 0) ? g_c : ((t & 1) ? g_cA : g_cB);
        float* hnext = (t & 1) ? g_hB : g_hA;
        float* cnext = (t & 1) ? g_cB : g_cA;
        const float* X = (t == 0) ? g_x0R : g_xfb;

        // layer 0: reads OLD h,c (reference quirk); c2 discarded
        run_cell(sm, X, FF, FF, g_pDW0, hcur, g_pDU0, DD,
                 g_pbD0, ccur, g_h0, g_c0);
        grid_bar(sense);
        // layer 1: x = layer0 h, h/c = OLD carry
        run_cell(sm, g_h0, DD, DD, g_pDW1, hcur, g_pDU1, DD,
                 g_pbD1, ccur, hnext, cnext);
        grid_bar(sense);

        // ---- dense: block = batch row; exact fp32 -> out, rounded -> xfb ----
        {
            const int row = blockIdx.x;
            float* hs = sm;            // 512 floats
            float* ps = sm + DD;       // 256 partials
            const float* hrow = hnext + (size_t)row * DD;
            #pragma unroll
            for (int k = tid; k < DD; k += 256) hs[k] = __ldcg(hrow + k);
            __syncthreads();

            const int col  = tid & 127;
            const int half = tid >> 7;
            const float* wp = dW + (size_t)(half * 256) * FF + col;
            float a0 = 0.f, a1 = 0.f;
            #pragma unroll 8
            for (int k = 0; k < 256; k += 2) {
                a0 += hs[half * 256 + k    ] * wp[(size_t)(k    ) * FF];
                a1 += hs[half * 256 + k + 1] * wp[(size_t)(k + 1) * FF];
            }
            ps[tid] = a0 + a1;
            __syncthreads();
            if (half == 0) {
                float v = ps[col] + ps[128 + col] + db[col];
                out[((size_t)row * TT + (TT - 1 - t)) * FF + col] = v;
                g_xfb[row * FF + col] = rna_tf32(v);
            }
        }
        grid_bar(sense);
    }
}

extern "C" void kernel_launch(void* const* d_in, const int* in_sizes, int n_in,
                              void* d_out, int out_size)
{
    const float* enc_in  = (const float*)d_in[0];
    const float* dec_in  = (const float*)d_in[1];
    const float* enc_W0  = (const float*)d_in[2];
    const float* enc_U0  = (const float*)d_in[3];
    const float* enc_b0  = (const float*)d_in[4];
    const float* enc_W1  = (const float*)d_in[5];
    const float* enc_U1  = (const float*)d_in[6];
    const float* enc_b1  = (const float*)d_in[7];
    const float* dec_W0  = (const float*)d_in[8];
    const float* dec_U0  = (const float*)d_in[9];
    const float* dec_b0  = (const float*)d_in[10];
    const float* dec_W1  = (const float*)d_in[11];
    const float* dec_U1  = (const float*)d_in[12];
    const float* dec_b1  = (const float*)d_in[13];
    const float* dense_W = (const float*)d_in[14];
    const float* dense_b = (const float*)d_in[15];
    float* out = (float*)d_out;

    cudaFuncSetAttribute(persist_kernel, cudaFuncAttributeMaxDynamicSharedMemorySize, SMEM_BYTES);

    float *h, *c, *Wsum;
    float *pEW0, *pEU0, *pW1s, *pDW0, *pDU0, *pDW1, *pDU1;
    float *pbE0, *pbE1, *pbD0, *pbD1, *encR, *x0R;
    unsigned* barp;
    cudaGetSymbolAddress((void**)&h,    g_h);
    cudaGetSymbolAddress((void**)&c,    g_c);
    cudaGetSymbolAddress((void**)&Wsum, g_Wsum);
    cudaGetSymbolAddress((void**)&pEW0, g_pEW0);
    cudaGetSymbolAddress((void**)&pEU0, g_pEU0);
    cudaGetSymbolAddress((void**)&pW1s, g_pW1s);
    cudaGetSymbolAddress((void**)&pDW0, g_pDW0);
    cudaGetSymbolAddress((void**)&pDU0, g_pDU0);
    cudaGetSymbolAddress((void**)&pDW1, g_pDW1);
    cudaGetSymbolAddress((void**)&pDU1, g_pDU1);
    cudaGetSymbolAddress((void**)&pbE0, g_pbE0);
    cudaGetSymbolAddress((void**)&pbE1, g_pbE1);
    cudaGetSymbolAddress((void**)&pbD0, g_pbD0);
    cudaGetSymbolAddress((void**)&pbD1, g_pbD1);
    cudaGetSymbolAddress((void**)&encR, g_encR);
    cudaGetSymbolAddress((void**)&x0R,  g_x0R);
    cudaGetSymbolAddress((void**)&barp, g_bar);

    // -------- preprocessing --------
    cudaMemsetAsync(h, 0, BB * DD * sizeof(float));
    cudaMemsetAsync(c, 0, BB * DD * sizeof(float));
    cudaMemsetAsync(barp, 0, 2 * sizeof(unsigned));

    { int n = BB * TT * FF; round_copy_kernel<<<(n + 255) / 256, 256>>>(enc_in, encR, n); }
    round_slice0_kernel<<<(BB * FF + 255) / 256, 256>>>(dec_in, x0R);

    { int n = DD * NG; add_mats_kernel<<<(n + 255) / 256, 256>>>(enc_W1, enc_U1, Wsum, n); }

    permute_mat_kernel<<<(NG * FF + 255) / 256, 256>>>(enc_W0, pEW0, FF, 7);
    permute_mat_kernel<<<(NG * DD + 255) / 256, 256>>>(enc_U0, pEU0, DD, 9);
    permute_mat_kernel<<<(NG * DD + 255) / 256, 256>>>(Wsum,   pW1s, DD, 9);
    permute_mat_kernel<<<(NG * FF + 255) / 256, 256>>>(dec_W0, pDW0, FF, 7);
    permute_mat_kernel<<<(NG * DD + 255) / 256, 256>>>(dec_U0, pDU0, DD, 9);
    permute_mat_kernel<<<(NG * DD + 255) / 256, 256>>>(dec_W1, pDW1, DD, 9);
    permute_mat_kernel<<<(NG * DD + 255) / 256, 256>>>(dec_U1, pDU1, DD, 9);

    permute_bias_kernel<<<8, 256>>>(enc_b0, pbE0);
    permute_bias_kernel<<<8, 256>>>(enc_b1, pbE1);
    permute_bias_kernel<<<8, 256>>>(dec_b0, pbD0);
    permute_bias_kernel<<<8, 256>>>(dec_b1, pbD1);

    // -------- the whole recurrence in one persistent kernel --------
    persist_kernel<<<NBLOCKS, 256, SMEM_BYTES>>>(dense_W, dense_b, out);
}